// round 12
// baseline (speedup 1.0000x reference)
#include <cuda_runtime.h>
#include <cuda_fp16.h>
#include <math.h>
#include <stdint.h>

#define DIM    768
#define HEADS  6
#define HDIM   128
#define HID    192
#define BATCH  4
#define NQ     4096
#define NV     21504
#define MQ     (BATCH*NQ)     // 16384
#define MV     (BATCH*NV)     // 86016
#define NFA    216

// ---------------- helpers ----------------------------------------------------
__device__ __forceinline__ uint32_t smem_u32(const void* p) {
    uint32_t a;
    asm("{ .reg .u64 t; cvta.to.shared.u64 t, %1; cvt.u32.u64 %0, t; }" : "=r"(a) : "l"(p));
    return a;
}
__device__ __forceinline__ void cp16(uint32_t s, const void* g) {
    asm volatile("cp.async.cg.shared.global [%0], [%1], 16;" :: "r"(s), "l"(g));
}
__device__ __forceinline__ void cp_commit() { asm volatile("cp.async.commit_group;"); }
__device__ __forceinline__ void cp_wait0()  { asm volatile("cp.async.wait_group 0;"); }
__device__ __forceinline__ void cp_wait1()  { asm volatile("cp.async.wait_group 1;"); }

__device__ __forceinline__ void ldm4(uint32_t* r, uint32_t a) {
    asm volatile("ldmatrix.sync.aligned.m8n8.x4.shared.b16 {%0,%1,%2,%3}, [%4];"
        : "=r"(r[0]), "=r"(r[1]), "=r"(r[2]), "=r"(r[3]) : "r"(a));
}
__device__ __forceinline__ void mma16816(float* c, const uint32_t* a, const uint32_t* b) {
    asm volatile("mma.sync.aligned.m16n8k16.row.col.f32.f16.f16.f32 "
        "{%0,%1,%2,%3}, {%4,%5,%6,%7}, {%8,%9}, {%0,%1,%2,%3};"
        : "+f"(c[0]), "+f"(c[1]), "+f"(c[2]), "+f"(c[3])
        : "r"(a[0]), "r"(a[1]), "r"(a[2]), "r"(a[3]), "r"(b[0]), "r"(b[1]));
}

// ---------------- scratch ----------------------------------------------------
__device__ __align__(16) float  g_qf  [(size_t)MQ*DIM];
__device__ __align__(16) __half g_qh  [(size_t)MQ*DIM];
__device__ __align__(16) __half g_fnh [(size_t)MV*DIM];
__device__ __align__(16) __half g_vb  [(size_t)MV*DIM];   // PERMUTED [b][h][pos][128]
__device__ __align__(16) float  g_fa  [(size_t)MQ*NFA];
__device__ __align__(16) float  g_fab [256];
__device__ __align__(16) __half g_sph [(size_t)MQ*DIM];
__device__ __align__(16) float  g_x   [(size_t)MQ*DIM];
__device__ __align__(16) __half g_xlh [(size_t)MQ*DIM];
__device__ __align__(16) float  g_y   [(size_t)MQ*HID];
__device__ __align__(16) __half g_ygh [(size_t)MQ*HID];
__device__ __align__(16) __half g_wv [768*768];
__device__ __align__(16) __half g_wo [768*768];
__device__ __align__(16) __half g_wfa[256*768];
__device__ __align__(16) __half g_w1 [256*768];
__device__ __align__(16) __half g_w2 [768*192];

// ---------------- weight transpose ------------------------------------------
__global__ __launch_bounds__(256)
void wprep_kernel(const float* __restrict__ W, __half* __restrict__ T,
                  int N, int Npad, int K)
{
    int idx = blockIdx.x * 256 + threadIdx.x;
    if (idx >= Npad * K) return;
    int n = idx / K, k = idx - n * K;
    float v = (n < N) ? W[(size_t)k * N + n] : 0.f;
    T[idx] = __float2half(v);
}

__global__ __launch_bounds__(256)
void wprep_merged_kernel(const float* __restrict__ Woff, const float* __restrict__ Waw,
                         __half* __restrict__ T)
{
    int idx = blockIdx.x * 256 + threadIdx.x;
    if (idx >= 256 * 768) return;
    int n = idx / 768, k = idx - n * 768;
    float v = 0.f;
    if (n < 144)      v = Woff[(size_t)k * 144 + n];
    else if (n < 216) v = Waw [(size_t)k * 72 + (n - 144)];
    T[idx] = __float2half(v);
}
__global__ void biascat_kernel(const float* __restrict__ ob, const float* __restrict__ ab,
                               float* __restrict__ out)
{
    int i = threadIdx.x;
    out[i] = (i < 144) ? ob[i] : (i < 216 ? ab[i - 144] : 0.f);
}

// ---------------- LayerNorm (768), warp-per-row, 512 threads -----------------
__global__ __launch_bounds__(512)
void ln_kernel(const float* __restrict__ in, const float* __restrict__ g,
               const float* __restrict__ b, float* __restrict__ outf,
               __half* __restrict__ outh)
{
    const int row  = blockIdx.x * 16 + (threadIdx.x >> 5);
    const int lane = threadIdx.x & 31;
    const float4* x4 = reinterpret_cast<const float4*>(in + (size_t)row * DIM);
    float4 v[6];
    float s = 0.f, ss = 0.f;
    #pragma unroll
    for (int j = 0; j < 6; j++) {
        v[j] = x4[lane + 32 * j];
        s  += v[j].x + v[j].y + v[j].z + v[j].w;
        ss += v[j].x * v[j].x + v[j].y * v[j].y + v[j].z * v[j].z + v[j].w * v[j].w;
    }
    #pragma unroll
    for (int o = 16; o > 0; o >>= 1) {
        s  += __shfl_xor_sync(0xffffffffu, s,  o);
        ss += __shfl_xor_sync(0xffffffffu, ss, o);
    }
    const float m = s * (1.f / DIM);
    const float r = rsqrtf(ss * (1.f / DIM) - m * m + 1e-6f);
    const float4* g4 = reinterpret_cast<const float4*>(g);
    const float4* b4 = reinterpret_cast<const float4*>(b);
    float4*       f4 = outf ? reinterpret_cast<float4*>(outf + (size_t)row * DIM) : nullptr;
    uint2*        h4 = reinterpret_cast<uint2*>(outh + (size_t)row * DIM);
    #pragma unroll
    for (int j = 0; j < 6; j++) {
        int i = lane + 32 * j;
        float4 gg = g4[i], bb = b4[i];
        float o0 = (v[j].x - m) * r * gg.x + bb.x;
        float o1 = (v[j].y - m) * r * gg.y + bb.y;
        float o2 = (v[j].z - m) * r * gg.z + bb.z;
        float o3 = (v[j].w - m) * r * gg.w + bb.w;
        if (f4) f4[i] = make_float4(o0, o1, o2, o3);
        __half2 p0 = __floats2half2_rn(o0, o1);
        __half2 p1 = __floats2half2_rn(o2, o3);
        uint2 u;
        u.x = *reinterpret_cast<uint32_t*>(&p0);
        u.y = *reinterpret_cast<uint32_t*>(&p1);
        h4[i] = u;
    }
}

// ---------------- fp16 mma.sync GEMM, 3-stage cp.async pipeline --------------
// If Cb != null: permuted fp16 write Cb[((permB*6+col/128)*NV + row)*128 + col%128]
// (caller passes per-batch A pointer; row is LOCAL, M == NV in that case).
__global__ __launch_bounds__(256, 2)
void mma_gemm(const __half* __restrict__ A, const __half* __restrict__ B,
              const float* __restrict__ bias, const float* __restrict__ add1,
              const float* __restrict__ add2, float* __restrict__ C,
              __half* __restrict__ Cb, int permB, int M, int N, int ldc, int K)
{
    extern __shared__ char smraw[];
    char* sm = (char*)(((uintptr_t)smraw + 1023) & ~(uintptr_t)1023);
    const uint32_t smBase = smem_u32(sm);

    const int tid  = threadIdx.x;
    const int lane = tid & 31, wid = tid >> 5;
    const int wm = (wid & 3) * 32;
    const int wn = (wid >> 2) * 64;
    const int m0 = blockIdx.y * 128, n0 = blockIdx.x * 128;

    const size_t strA = (size_t)K * 2;
    const char* gA = (const char*)A + (size_t)m0 * strA;
    const char* gB = (const char*)B + (size_t)n0 * strA;

    const int aRow = lane & 15;
    const int aCol = (lane >> 4) * 16;
    const int bRowOff = ((lane & 16) >> 1) + (lane & 7);
    const int bCol = (lane & 8) * 2;

    uint32_t aBase[2], aXor[2];
    #pragma unroll
    for (int mt = 0; mt < 2; mt++) {
        int row = wm + mt * 16 + aRow;
        aBase[mt] = (uint32_t)(row * 128);
        aXor[mt]  = (uint32_t)(aCol ^ ((row & 7) * 16));
    }
    uint32_t bBase[4], bXor[4];
    #pragma unroll
    for (int np = 0; np < 4; np++) {
        int row = wn + np * 16 + bRowOff;
        bBase[np] = (uint32_t)(16384 + row * 128);
        bXor[np]  = (uint32_t)(bCol ^ ((row & 7) * 16));
    }

    float acc[2][8][4];
    #pragma unroll
    for (int i = 0; i < 2; i++)
        #pragma unroll
        for (int j = 0; j < 8; j++)
            #pragma unroll
            for (int k = 0; k < 4; k++) acc[i][j][k] = 0.f;

    const int nCh = K >> 6;

    #define LOAD_CHUNK(kc_, st_) do {                                           \
        uint32_t dst = smBase + (uint32_t)(st_) * 32768u;                       \
        size_t kb_ = (size_t)(kc_) * 128;                                       \
        _Pragma("unroll")                                                       \
        for (int i_ = 0; i_ < 4; i_++) {                                        \
            int u_ = tid + 256 * i_;                                            \
            int r_ = u_ >> 3, c_ = u_ & 7;                                      \
            uint32_t off_ = (uint32_t)(r_ * 128 + c_ * 16);                     \
            uint32_t sw_ = off_ ^ ((off_ >> 3) & 0x70);                         \
            size_t go_ = (size_t)r_ * strA + kb_ + (size_t)c_ * 16;             \
            cp16(dst + sw_,         gA + go_);                                  \
            cp16(dst + 16384 + sw_, gB + go_);                                  \
        }                                                                       \
    } while (0)

    LOAD_CHUNK(0, 0);
    cp_commit();
    if (nCh > 1) { LOAD_CHUNK(1, 1); cp_commit(); }

    for (int kc = 0; kc < nCh; kc++) {
        if (kc + 1 < nCh) cp_wait1(); else cp_wait0();
        __syncthreads();
        if (kc + 2 < nCh) {
            int st2 = (kc + 2) % 3;
            LOAD_CHUNK(kc + 2, st2);
            cp_commit();
        }
        const uint32_t stBase = smBase + (uint32_t)(kc % 3) * 32768u;
        #pragma unroll
        for (int ks = 0; ks < 4; ks++) {
            const uint32_t kb = (uint32_t)(ks * 32);
            uint32_t ah[2][4], bb[8][2];
            #pragma unroll
            for (int mt = 0; mt < 2; mt++)
                ldm4(ah[mt], stBase + aBase[mt] + (kb ^ aXor[mt]));
            #pragma unroll
            for (int np = 0; np < 4; np++)
                ldm4(&bb[2 * np][0], stBase + bBase[np] + (kb ^ bXor[np]));
            #pragma unroll
            for (int mt = 0; mt < 2; mt++)
                #pragma unroll
                for (int nt = 0; nt < 8; nt++) mma16816(acc[mt][nt], ah[mt], bb[nt]);
        }
    }
    #undef LOAD_CHUNK

    #pragma unroll
    for (int mt = 0; mt < 2; mt++) {
        #pragma unroll
        for (int nt = 0; nt < 8; nt++) {
            int row = m0 + wm + mt * 16 + (lane >> 2);
            int col = n0 + wn + nt * 8 + 2 * (lane & 3);
            if (col < N) {
                #pragma unroll
                for (int half_ = 0; half_ < 2; half_++) {
                    int rr = row + half_ * 8;
                    size_t i0 = (size_t)rr * ldc + col;
                    float v0 = acc[mt][nt][half_ * 2 + 0] + bias[col];
                    float v1 = acc[mt][nt][half_ * 2 + 1] + bias[col + 1];
                    if (add1) { v0 += add1[i0]; v1 += add1[i0 + 1]; }
                    if (add2) { v0 += add2[i0]; v1 += add2[i0 + 1]; }
                    if (C) { C[i0] = v0; C[i0 + 1] = v1; }
                    if (Cb) {
                        int hh = col >> 7, ch = col & 127;
                        size_t pi = (((size_t)(permB * 6 + hh)) * NV + rr) * 128 + ch;
                        Cb[pi] = __float2half(v0); Cb[pi + 1] = __float2half(v1);
                    }
                }
            }
        }
    }
}

// ---------------- deformable sampling: 2 queries/block, permuted v -----------
__global__ __launch_bounds__(384)
void sample_kernel(const float* __restrict__ refp, const float* __restrict__ fa,
                   const __half* __restrict__ v, __half* __restrict__ outh, int bqOff)
{
    const int slot = threadIdx.x / 192;
    const int sub  = threadIdx.x % 192;
    const int bq   = bqOff + blockIdx.x * 2 + slot;
    const int b    = bq / NQ;
    __shared__ float s_fa[2][NFA], s_w[2][72], s_x[2][72], s_y[2][72], s_ref[2][6];
    for (int i = sub; i < NFA; i += 192) s_fa[slot][i] = fa[(size_t)bq * NFA + i];
    if (sub < 6) s_ref[slot][sub] = refp[(size_t)bq * 6 + sub];
    __syncthreads();

    const int Hl[3] = {128, 64, 32};
    const int Wl[3] = {128, 64, 32};
    const int st[3] = {0, 16384, 20480};

    if (sub < 6) {
        int h = sub;
        const float* wrow = &s_fa[slot][144 + h * 12];
        float mx = -1e30f;
        for (int i = 0; i < 12; i++) mx = fmaxf(mx, wrow[i]);
        float sum = 0.f;
        float e[12];
        for (int i = 0; i < 12; i++) { e[i] = expf(wrow[i] - mx); sum += e[i]; }
        float inv = 1.f / sum;
        for (int i = 0; i < 12; i++) s_w[slot][h * 12 + i] = e[i] * inv;
    }
    if (sub < 72) {
        int h = sub / 12, lp = sub % 12, l = lp >> 2, p = lp & 3;
        float ox = s_fa[slot][h * 24 + l * 8 + p * 2 + 0];
        float oy = s_fa[slot][h * 24 + l * 8 + p * 2 + 1];
        float lx = s_ref[slot][l * 2 + 0] + ox / (float)Wl[l];
        float ly = s_ref[slot][l * 2 + 1] + oy / (float)Hl[l];
        s_x[slot][sub] = lx * (float)Wl[l] - 0.5f;
        s_y[slot][sub] = ly * (float)Hl[l] - 0.5f;
    }
    __syncthreads();

    const int h  = sub >> 5;
    const int c4 = (sub & 31) * 4;
    float a0 = 0.f, a1 = 0.f, a2 = 0.f, a3 = 0.f;
    #pragma unroll
    for (int lp = 0; lp < 12; lp++) {
        const int l  = lp >> 2;
        const int W_ = Wl[l], H_ = Hl[l];
        float w  = s_w[slot][h * 12 + lp];
        float x  = s_x[slot][h * 12 + lp];
        float y  = s_y[slot][h * 12 + lp];
        float x0f = floorf(x), y0f = floorf(y);
        float wx = x - x0f, wy = y - y0f;
        int x0 = (int)x0f, y0 = (int)y0f;
        const __half* base = v + (((size_t)(b * 6 + h)) * NV + st[l]) * 128 + c4;
        float w00 = w * (1.f - wx) * (1.f - wy);
        float w10 = w * wx * (1.f - wy);
        float w01 = w * (1.f - wx) * wy;
        float w11 = w * wx * wy;
        #pragma unroll
        for (int cr = 0; cr < 4; cr++) {
            int xi = x0 + (cr & 1), yi = y0 + (cr >> 1);
            float cw = (cr == 0) ? w00 : (cr == 1) ? w10 : (cr == 2) ? w01 : w11;
            if (xi >= 0 && xi < W_ && yi >= 0 && yi < H_ && cw != 0.f) {
                uint2 u = *reinterpret_cast<const uint2*>(base + (size_t)(yi * W_ + xi) * 128);
                float2 p0 = __half22float2(*reinterpret_cast<__half2*>(&u.x));
                float2 p1 = __half22float2(*reinterpret_cast<__half2*>(&u.y));
                a0 += cw * p0.x;
                a1 += cw * p0.y;
                a2 += cw * p1.x;
                a3 += cw * p1.y;
            }
        }
    }
    size_t o = (size_t)bq * DIM + h * HDIM + c4;
    __half2 q0 = __floats2half2_rn(a0, a1);
    __half2 q1 = __floats2half2_rn(a2, a3);
    uint2 u;
    u.x = *reinterpret_cast<uint32_t*>(&q0);
    u.y = *reinterpret_cast<uint32_t*>(&q1);
    *reinterpret_cast<uint2*>(outh + o) = u;
}

// ---------------- depthwise 3x3 + GELU, 4 vertical pixels/thread -------------
__global__ __launch_bounds__(HID)
void dwconv_gelu_kernel(const float* __restrict__ y, const float* __restrict__ w,
                        const float* __restrict__ bias, __half* __restrict__ outh)
{
    const int idx = blockIdx.x;
    const int b   = idx >> 10;
    const int rem = idx & 1023;
    const int h0  = (rem >> 6) * 4;
    const int ww  = rem & 63;
    const int c   = threadIdx.x;

    float wreg[9];
    #pragma unroll
    for (int t = 0; t < 9; t++) wreg[t] = w[t * HID + c];
    const float bs = bias[c];

    float vin[6][3];
    #pragma unroll
    for (int rr = 0; rr < 6; rr++) {
        int hh = h0 + rr - 1;
        #pragma unroll
        for (int cc = 0; cc < 3; cc++) {
            int xx = ww + cc - 1;
            vin[rr][cc] = (hh >= 0 && hh < 64 && xx >= 0 && xx < 64)
                ? y[((size_t)(b * 4096 + hh * 64 + xx)) * HID + c] : 0.f;
        }
    }
    #pragma unroll
    for (int p = 0; p < 4; p++) {
        float acc = bs;
        #pragma unroll
        for (int ky = 0; ky < 3; ky++)
            #pragma unroll
            for (int kx = 0; kx < 3; kx++)
                acc += vin[p + ky][kx] * wreg[ky * 3 + kx];
        float g = 0.5f * acc * (1.f + erff(acc * 0.70710678118654752f));
        outh[((size_t)(b * 4096 + (h0 + p) * 64 + ww)) * HID + c] = __float2half(g);
    }
}

// ---------------- host orchestration ----------------------------------------
#define GEMM_SMEM (98304 + 1024)

extern "C" void kernel_launch(void* const* d_in, const int* in_sizes, int n_in,
                              void* d_out, int out_size)
{
    const float* query = (const float*)d_in[0];
    const float* refp  = (const float*)d_in[1];
    const float* feat  = (const float*)d_in[2];
    const int wb = n_in - 20;
    const float* qn_g  = (const float*)d_in[wb + 0];
    const float* qn_b  = (const float*)d_in[wb + 1];
    const float* fn_g  = (const float*)d_in[wb + 2];
    const float* fn_b  = (const float*)d_in[wb + 3];
    const float* off_w = (const float*)d_in[wb + 4];
    const float* off_b = (const float*)d_in[wb + 5];
    const float* aw_w  = (const float*)d_in[wb + 6];
    const float* aw_b  = (const float*)d_in[wb + 7];
    const float* vp_w  = (const float*)d_in[wb + 8];
    const float* vp_b  = (const float*)d_in[wb + 9];
    const float* op_w  = (const float*)d_in[wb + 10];
    const float* op_b  = (const float*)d_in[wb + 11];
    const float* ffn_g = (const float*)d_in[wb + 12];
    const float* ffn_b = (const float*)d_in[wb + 13];
    const float* fc1_w = (const float*)d_in[wb + 14];
    const float* fc1_b = (const float*)d_in[wb + 15];
    const float* dw_w  = (const float*)d_in[wb + 16];
    const float* dw_b  = (const float*)d_in[wb + 17];
    const float* fc2_w = (const float*)d_in[wb + 18];
    const float* fc2_b = (const float*)d_in[wb + 19];

    static cudaStream_t s1 = nullptr, s2 = nullptr;
    static cudaEvent_t e0, ewfa, ew, eln[BATCH], evp[BATCH];
    if (!s1) {
        cudaStreamCreateWithFlags(&s1, cudaStreamNonBlocking);
        cudaStreamCreateWithFlags(&s2, cudaStreamNonBlocking);
        cudaEventCreateWithFlags(&e0,   cudaEventDisableTiming);
        cudaEventCreateWithFlags(&ewfa, cudaEventDisableTiming);
        cudaEventCreateWithFlags(&ew,   cudaEventDisableTiming);
        for (int b = 0; b < BATCH; b++) {
            cudaEventCreateWithFlags(&eln[b], cudaEventDisableTiming);
            cudaEventCreateWithFlags(&evp[b], cudaEventDisableTiming);
        }
        cudaFuncSetAttribute(mma_gemm, cudaFuncAttributeMaxDynamicSharedMemorySize, GEMM_SMEM);
    }

    float *qf, *fa, *fab, *x, *y;
    __half *qh, *fnh, *vb, *sph, *xlh, *ygh;
    __half *wv, *wo, *wfa, *w1, *w2;
    cudaGetSymbolAddress((void**)&qf,  g_qf);  cudaGetSymbolAddress((void**)&qh,  g_qh);
    cudaGetSymbolAddress((void**)&fnh, g_fnh); cudaGetSymbolAddress((void**)&vb,  g_vb);
    cudaGetSymbolAddress((void**)&fa,  g_fa);  cudaGetSymbolAddress((void**)&fab, g_fab);
    cudaGetSymbolAddress((void**)&sph, g_sph); cudaGetSymbolAddress((void**)&x,   g_x);
    cudaGetSymbolAddress((void**)&xlh, g_xlh); cudaGetSymbolAddress((void**)&y,   g_y);
    cudaGetSymbolAddress((void**)&ygh, g_ygh);
    cudaGetSymbolAddress((void**)&wv,  g_wv);  cudaGetSymbolAddress((void**)&wo,  g_wo);
    cudaGetSymbolAddress((void**)&wfa, g_wfa); cudaGetSymbolAddress((void**)&w1,  g_w1);
    cudaGetSymbolAddress((void**)&w2,  g_w2);

    // fork
    cudaEventRecord(e0, 0);
    cudaStreamWaitEvent(s1, e0, 0);
    cudaStreamWaitEvent(s2, e0, 0);

    // s1: vp weight prep, then per-batch vp GEMM chunks (each gated on its LN chunk)
    wprep_kernel<<<(768*768 + 255)/256, 256, 0, s1>>>(vp_w, wv, 768, 768, 768);

    // s2: fa weight prep FIRST (tiny), then per-batch ln_feat chunks, then tail wpreps
    wprep_merged_kernel<<<(256*768 + 255)/256, 256, 0, s2>>>(off_w, aw_w, wfa);
    biascat_kernel<<<1, 256, 0, s2>>>(off_b, aw_b, fab);
    cudaEventRecord(ewfa, s2);
    for (int b = 0; b < BATCH; b++) {
        ln_kernel<<<NV/16, 512, 0, s2>>>(feat + (size_t)b*NV*DIM, fn_g, fn_b,
                                         nullptr, fnh + (size_t)b*NV*DIM);
        cudaEventRecord(eln[b], s2);
        cudaStreamWaitEvent(s1, eln[b], 0);
        mma_gemm<<<dim3(6, NV/128), 256, GEMM_SMEM, s1>>>(
            fnh + (size_t)b*NV*DIM, wv, vp_b, nullptr, nullptr,
            nullptr, vb, b, NV, 768, 768, 768);
        cudaEventRecord(evp[b], s1);
    }
    wprep_kernel<<<(768*768 + 255)/256, 256, 0, s2>>>(op_w,  wo, 768, 768, 768);
    wprep_kernel<<<(256*768 + 255)/256, 256, 0, s2>>>(fc1_w, w1, 192, 256, 768);
    wprep_kernel<<<(768*192 + 255)/256, 256, 0, s2>>>(fc2_w, w2, 768, 768, 192);
    cudaEventRecord(ew, s2);   // JOIN POINT for s2 (was missing -> capture failure)

    // s0: query branch + fa GEMM + per-batch sampling + tail
    ln_kernel<<<MQ/16, 512>>>(query, qn_g, qn_b, qf, qh);
    cudaStreamWaitEvent(0, ewfa, 0);
    mma_gemm<<<dim3(2, MQ/128), 256, GEMM_SMEM>>>(qh, wfa, fab, nullptr, nullptr,
                                                  fa, nullptr, 0, MQ, NFA, NFA, 768);
    for (int b = 0; b < BATCH; b++) {
        cudaStreamWaitEvent(0, evp[b], 0);   // joins s1 work incrementally (evp[3] = all of s1)
        sample_kernel<<<NQ/2, 384>>>(refp, fa, vb, sph, b * NQ);
    }
    cudaStreamWaitEvent(0, ew, 0);           // join s2's tail wpreps before using wo/w1/w2
    mma_gemm<<<dim3(6, MQ/128), 256, GEMM_SMEM>>>(sph, wo, op_b, qf, query,
                                                  x, nullptr, 0, MQ, 768, 768, 768);
    ln_kernel<<<MQ/16, 512>>>(x, ffn_g, ffn_b, nullptr, xlh);
    mma_gemm<<<dim3(2, MQ/128), 256, GEMM_SMEM>>>(xlh, w1, fc1_b, nullptr, nullptr,
                                                  y, nullptr, 0, MQ, 192, 192, 768);
    dwconv_gelu_kernel<<<BATCH*16*64, HID>>>(y, dw_w, dw_b, ygh);
    mma_gemm<<<dim3(6, MQ/128), 256, GEMM_SMEM>>>(ygh, w2, fc2_b, x, nullptr,
                                                  (float*)d_out, nullptr, 0, MQ, 768, 768, 192);
}

// round 16
// speedup vs baseline: 1.0031x; 1.0031x over previous
#include <cuda_runtime.h>
#include <cuda_fp16.h>
#include <math.h>
#include <stdint.h>

#define DIM    768
#define HEADS  6
#define HDIM   128
#define HID    192
#define BATCH  4
#define NQ     4096
#define NV     21504
#define MQ     (BATCH*NQ)     // 16384
#define MV     (BATCH*NV)     // 86016
#define NFA    216

// ---------------- helpers ----------------------------------------------------
__device__ __forceinline__ uint32_t smem_u32(const void* p) {
    uint32_t a;
    asm("{ .reg .u64 t; cvta.to.shared.u64 t, %1; cvt.u32.u64 %0, t; }" : "=r"(a) : "l"(p));
    return a;
}
__device__ __forceinline__ void cp16(uint32_t s, const void* g) {
    asm volatile("cp.async.cg.shared.global [%0], [%1], 16;" :: "r"(s), "l"(g));
}
__device__ __forceinline__ void cp_commit() { asm volatile("cp.async.commit_group;"); }
__device__ __forceinline__ void cp_wait0()  { asm volatile("cp.async.wait_group 0;"); }
__device__ __forceinline__ void cp_wait1()  { asm volatile("cp.async.wait_group 1;"); }

__device__ __forceinline__ void ldm4(uint32_t* r, uint32_t a) {
    asm volatile("ldmatrix.sync.aligned.m8n8.x4.shared.b16 {%0,%1,%2,%3}, [%4];"
        : "=r"(r[0]), "=r"(r[1]), "=r"(r[2]), "=r"(r[3]) : "r"(a));
}
__device__ __forceinline__ void mma16816(float* c, const uint32_t* a, const uint32_t* b) {
    asm volatile("mma.sync.aligned.m16n8k16.row.col.f32.f16.f16.f32 "
        "{%0,%1,%2,%3}, {%4,%5,%6,%7}, {%8,%9}, {%0,%1,%2,%3};"
        : "+f"(c[0]), "+f"(c[1]), "+f"(c[2]), "+f"(c[3])
        : "r"(a[0]), "r"(a[1]), "r"(a[2]), "r"(a[3]), "r"(b[0]), "r"(b[1]));
}

// ---------------- scratch ----------------------------------------------------
__device__ __align__(16) __half g_qh  [(size_t)MQ*DIM];
__device__ __align__(16) __half g_fnh [(size_t)MV*DIM];
__device__ __align__(16) __half g_vb  [(size_t)MV*DIM];   // PERMUTED [b][h][pos][128]
__device__ __align__(16) float  g_fa  [(size_t)MQ*NFA];
__device__ __align__(16) float  g_fab [256];
__device__ __align__(16) __half g_sph [(size_t)MQ*DIM];
__device__ __align__(16) float  g_x   [(size_t)MQ*DIM];
__device__ __align__(16) __half g_xlh [(size_t)MQ*DIM];
__device__ __align__(16) __half g_yh  [(size_t)MQ*HID];
__device__ __align__(16) __half g_ygh [(size_t)MQ*HID];
__device__ __align__(16) __half g_wv [768*768];
__device__ __align__(16) __half g_wo [768*768];
__device__ __align__(16) __half g_wfa[256*768];
__device__ __align__(16) __half g_w1 [256*768];
__device__ __align__(16) __half g_w2 [768*192];

// ---------------- weight transpose ------------------------------------------
__global__ __launch_bounds__(256)
void wprep_kernel(const float* __restrict__ W, __half* __restrict__ T,
                  int N, int Npad, int K)
{
    int idx = blockIdx.x * 256 + threadIdx.x;
    if (idx >= Npad * K) return;
    int n = idx / K, k = idx - n * K;
    float v = (n < N) ? W[(size_t)k * N + n] : 0.f;
    T[idx] = __float2half(v);
}

__global__ __launch_bounds__(256)
void wprep_merged_kernel(const float* __restrict__ Woff, const float* __restrict__ Waw,
                         __half* __restrict__ T)
{
    int idx = blockIdx.x * 256 + threadIdx.x;
    if (idx >= 256 * 768) return;
    int n = idx / 768, k = idx - n * 768;
    float v = 0.f;
    if (n < 144)      v = Woff[(size_t)k * 144 + n];
    else if (n < 216) v = Waw [(size_t)k * 72 + (n - 144)];
    T[idx] = __float2half(v);
}
__global__ void biascat_kernel(const float* __restrict__ ob, const float* __restrict__ ab,
                               float* __restrict__ out)
{
    int i = threadIdx.x;
    out[i] = (i < 144) ? ob[i] : (i < 216 ? ab[i - 144] : 0.f);
}

// ---------------- LayerNorm (768), warp-per-row, two-pass (low-reg) ----------
__global__ __launch_bounds__(512)
void ln_kernel(const float* __restrict__ in, const float* __restrict__ g,
               const float* __restrict__ b, __half* __restrict__ outh)
{
    const int row  = blockIdx.x * 16 + (threadIdx.x >> 5);
    const int lane = threadIdx.x & 31;
    const float4* x4 = reinterpret_cast<const float4*>(in + (size_t)row * DIM);
    float s = 0.f, ss = 0.f;
    #pragma unroll
    for (int j = 0; j < 6; j++) {
        float4 t = x4[lane + 32 * j];
        s  += t.x + t.y + t.z + t.w;
        ss += t.x * t.x + t.y * t.y + t.z * t.z + t.w * t.w;
    }
    #pragma unroll
    for (int o = 16; o > 0; o >>= 1) {
        s  += __shfl_xor_sync(0xffffffffu, s,  o);
        ss += __shfl_xor_sync(0xffffffffu, ss, o);
    }
    const float m = s * (1.f / DIM);
    const float r = rsqrtf(ss * (1.f / DIM) - m * m + 1e-6f);
    const float4* g4 = reinterpret_cast<const float4*>(g);
    const float4* b4 = reinterpret_cast<const float4*>(b);
    uint2* h4 = reinterpret_cast<uint2*>(outh + (size_t)row * DIM);
    #pragma unroll
    for (int j = 0; j < 6; j++) {
        int i = lane + 32 * j;
        float4 t  = x4[i];           // second pass: L1 hit
        float4 gg = g4[i], bb = b4[i];
        float o0 = (t.x - m) * r * gg.x + bb.x;
        float o1 = (t.y - m) * r * gg.y + bb.y;
        float o2 = (t.z - m) * r * gg.z + bb.z;
        float o3 = (t.w - m) * r * gg.w + bb.w;
        __half2 p0 = __floats2half2_rn(o0, o1);
        __half2 p1 = __floats2half2_rn(o2, o3);
        uint2 u;
        u.x = *reinterpret_cast<uint32_t*>(&p0);
        u.y = *reinterpret_cast<uint32_t*>(&p1);
        h4[i] = u;
    }
}

// ---------------- fp16 mma.sync GEMM, 3-stage cp.async pipeline --------------
// adds: add1h (fp16, optional), add2 (fp32, optional).
// outputs: C fp32 (optional) and/or Cb fp16.
//   permuted==0: Cb plain at ldc.  permuted==1: Cb[((b*6+col/128)*NV+pos)*128+col%128].
__global__ __launch_bounds__(256, 2)
void mma_gemm(const __half* __restrict__ A, const __half* __restrict__ B,
              const float* __restrict__ bias, const __half* __restrict__ add1h,
              const float* __restrict__ add2, float* __restrict__ C,
              __half* __restrict__ Cb, int permuted, int M, int N, int ldc, int K)
{
    extern __shared__ char smraw[];
    char* sm = (char*)(((uintptr_t)smraw + 1023) & ~(uintptr_t)1023);
    const uint32_t smBase = smem_u32(sm);

    const int tid  = threadIdx.x;
    const int lane = tid & 31, wid = tid >> 5;
    const int wm = (wid & 3) * 32;
    const int wn = (wid >> 2) * 64;
    const int m0 = blockIdx.y * 128, n0 = blockIdx.x * 128;

    const size_t strA = (size_t)K * 2;
    const char* gA = (const char*)A + (size_t)m0 * strA;
    const char* gB = (const char*)B + (size_t)n0 * strA;

    const int aRow = lane & 15;
    const int aCol = (lane >> 4) * 16;
    const int bRowOff = ((lane & 16) >> 1) + (lane & 7);
    const int bCol = (lane & 8) * 2;

    uint32_t aBase[2], aXor[2];
    #pragma unroll
    for (int mt = 0; mt < 2; mt++) {
        int row = wm + mt * 16 + aRow;
        aBase[mt] = (uint32_t)(row * 128);
        aXor[mt]  = (uint32_t)(aCol ^ ((row & 7) * 16));
    }
    uint32_t bBase[4], bXor[4];
    #pragma unroll
    for (int np = 0; np < 4; np++) {
        int row = wn + np * 16 + bRowOff;
        bBase[np] = (uint32_t)(16384 + row * 128);
        bXor[np]  = (uint32_t)(bCol ^ ((row & 7) * 16));
    }

    float acc[2][8][4];
    #pragma unroll
    for (int i = 0; i < 2; i++)
        #pragma unroll
        for (int j = 0; j < 8; j++)
            #pragma unroll
            for (int k = 0; k < 4; k++) acc[i][j][k] = 0.f;

    const int nCh = K >> 6;

    #define LOAD_CHUNK(kc_, st_) do {                                           \
        uint32_t dst = smBase + (uint32_t)(st_) * 32768u;                       \
        size_t kb_ = (size_t)(kc_) * 128;                                       \
        _Pragma("unroll")                                                       \
        for (int i_ = 0; i_ < 4; i_++) {                                        \
            int u_ = tid + 256 * i_;                                            \
            int r_ = u_ >> 3, c_ = u_ & 7;                                      \
            uint32_t off_ = (uint32_t)(r_ * 128 + c_ * 16);                     \
            uint32_t sw_ = off_ ^ ((off_ >> 3) & 0x70);                         \
            size_t go_ = (size_t)r_ * strA + kb_ + (size_t)c_ * 16;             \
            cp16(dst + sw_,         gA + go_);                                  \
            cp16(dst + 16384 + sw_, gB + go_);                                  \
        }                                                                       \
    } while (0)

    LOAD_CHUNK(0, 0);
    cp_commit();
    if (nCh > 1) { LOAD_CHUNK(1, 1); cp_commit(); }

    for (int kc = 0; kc < nCh; kc++) {
        if (kc + 1 < nCh) cp_wait1(); else cp_wait0();
        __syncthreads();
        if (kc + 2 < nCh) {
            int st2 = (kc + 2) % 3;
            LOAD_CHUNK(kc + 2, st2);
            cp_commit();
        }
        const uint32_t stBase = smBase + (uint32_t)(kc % 3) * 32768u;
        #pragma unroll
        for (int ks = 0; ks < 4; ks++) {
            const uint32_t kb = (uint32_t)(ks * 32);
            uint32_t ah[2][4], bb[8][2];
            #pragma unroll
            for (int mt = 0; mt < 2; mt++)
                ldm4(ah[mt], stBase + aBase[mt] + (kb ^ aXor[mt]));
            #pragma unroll
            for (int np = 0; np < 4; np++)
                ldm4(&bb[2 * np][0], stBase + bBase[np] + (kb ^ bXor[np]));
            #pragma unroll
            for (int mt = 0; mt < 2; mt++)
                #pragma unroll
                for (int nt = 0; nt < 8; nt++) mma16816(acc[mt][nt], ah[mt], bb[nt]);
        }
    }
    #undef LOAD_CHUNK

    #pragma unroll
    for (int mt = 0; mt < 2; mt++) {
        #pragma unroll
        for (int nt = 0; nt < 8; nt++) {
            int row = m0 + wm + mt * 16 + (lane >> 2);
            int col = n0 + wn + nt * 8 + 2 * (lane & 3);
            if (col < N) {
                #pragma unroll
                for (int half_ = 0; half_ < 2; half_++) {
                    int rr = row + half_ * 8;
                    size_t i0 = (size_t)rr * ldc + col;
                    float v0 = acc[mt][nt][half_ * 2 + 0] + bias[col];
                    float v1 = acc[mt][nt][half_ * 2 + 1] + bias[col + 1];
                    if (add1h) { v0 += __half2float(add1h[i0]); v1 += __half2float(add1h[i0 + 1]); }
                    if (add2)  { v0 += add2[i0]; v1 += add2[i0 + 1]; }
                    if (C) { C[i0] = v0; C[i0 + 1] = v1; }
                    if (Cb) {
                        if (permuted) {
                            int bidx = rr / NV, pos = rr - bidx * NV;
                            int hh = col >> 7, ch = col & 127;
                            size_t pi = (((size_t)(bidx * 6 + hh)) * NV + pos) * 128 + ch;
                            Cb[pi] = __float2half(v0); Cb[pi + 1] = __float2half(v1);
                        } else {
                            Cb[i0] = __float2half(v0); Cb[i0 + 1] = __float2half(v1);
                        }
                    }
                }
            }
        }
    }
}

// ---------------- deformable sampling: 2 queries/block, permuted v -----------
__global__ __launch_bounds__(384)
void sample_kernel(const float* __restrict__ refp, const float* __restrict__ fa,
                   const __half* __restrict__ v, __half* __restrict__ outh)
{
    const int slot = threadIdx.x / 192;
    const int sub  = threadIdx.x % 192;
    const int bq   = blockIdx.x * 2 + slot;
    const int b    = bq / NQ;
    __shared__ float s_fa[2][NFA], s_w[2][72], s_x[2][72], s_y[2][72], s_ref[2][6];
    for (int i = sub; i < NFA; i += 192) s_fa[slot][i] = fa[(size_t)bq * NFA + i];
    if (sub < 6) s_ref[slot][sub] = refp[(size_t)bq * 6 + sub];
    __syncthreads();

    const int Hl[3] = {128, 64, 32};
    const int Wl[3] = {128, 64, 32};
    const int st[3] = {0, 16384, 20480};

    if (sub < 6) {
        int h = sub;
        const float* wrow = &s_fa[slot][144 + h * 12];
        float mx = -1e30f;
        for (int i = 0; i < 12; i++) mx = fmaxf(mx, wrow[i]);
        float sum = 0.f;
        float e[12];
        for (int i = 0; i < 12; i++) { e[i] = expf(wrow[i] - mx); sum += e[i]; }
        float inv = 1.f / sum;
        for (int i = 0; i < 12; i++) s_w[slot][h * 12 + i] = e[i] * inv;
    }
    if (sub < 72) {
        int h = sub / 12, lp = sub % 12, l = lp >> 2, p = lp & 3;
        float ox = s_fa[slot][h * 24 + l * 8 + p * 2 + 0];
        float oy = s_fa[slot][h * 24 + l * 8 + p * 2 + 1];
        float lx = s_ref[slot][l * 2 + 0] + ox / (float)Wl[l];
        float ly = s_ref[slot][l * 2 + 1] + oy / (float)Hl[l];
        s_x[slot][sub] = lx * (float)Wl[l] - 0.5f;
        s_y[slot][sub] = ly * (float)Hl[l] - 0.5f;
    }
    __syncthreads();

    const int h  = sub >> 5;
    const int c4 = (sub & 31) * 4;
    float a0 = 0.f, a1 = 0.f, a2 = 0.f, a3 = 0.f;
    #pragma unroll
    for (int lp = 0; lp < 12; lp++) {
        const int l  = lp >> 2;
        const int W_ = Wl[l], H_ = Hl[l];
        float w  = s_w[slot][h * 12 + lp];
        float x  = s_x[slot][h * 12 + lp];
        float y  = s_y[slot][h * 12 + lp];
        float x0f = floorf(x), y0f = floorf(y);
        float wx = x - x0f, wy = y - y0f;
        int x0 = (int)x0f, y0 = (int)y0f;
        const __half* base = v + (((size_t)(b * 6 + h)) * NV + st[l]) * 128 + c4;
        float w00 = w * (1.f - wx) * (1.f - wy);
        float w10 = w * wx * (1.f - wy);
        float w01 = w * (1.f - wx) * wy;
        float w11 = w * wx * wy;
        #pragma unroll
        for (int cr = 0; cr < 4; cr++) {
            int xi = x0 + (cr & 1), yi = y0 + (cr >> 1);
            float cw = (cr == 0) ? w00 : (cr == 1) ? w10 : (cr == 2) ? w01 : w11;
            if (xi >= 0 && xi < W_ && yi >= 0 && yi < H_ && cw != 0.f) {
                uint2 u = *reinterpret_cast<const uint2*>(base + (size_t)(yi * W_ + xi) * 128);
                float2 p0 = __half22float2(*reinterpret_cast<__half2*>(&u.x));
                float2 p1 = __half22float2(*reinterpret_cast<__half2*>(&u.y));
                a0 += cw * p0.x;
                a1 += cw * p0.y;
                a2 += cw * p1.x;
                a3 += cw * p1.y;
            }
        }
    }
    size_t o = (size_t)bq * DIM + h * HDIM + c4;
    __half2 q0 = __floats2half2_rn(a0, a1);
    __half2 q1 = __floats2half2_rn(a2, a3);
    uint2 u;
    u.x = *reinterpret_cast<uint32_t*>(&q0);
    u.y = *reinterpret_cast<uint32_t*>(&q1);
    *reinterpret_cast<uint2*>(outh + o) = u;
}

// ---------------- depthwise 3x3 + GELU (fp16 in), 4 vertical px/thread -------
__global__ __launch_bounds__(HID)
void dwconv_gelu_kernel(const __half* __restrict__ y, const float* __restrict__ w,
                        const float* __restrict__ bias, __half* __restrict__ outh)
{
    const int idx = blockIdx.x;
    const int b   = idx >> 10;
    const int rem = idx & 1023;
    const int h0  = (rem >> 6) * 4;
    const int ww  = rem & 63;
    const int c   = threadIdx.x;

    float wreg[9];
    #pragma unroll
    for (int t = 0; t < 9; t++) wreg[t] = w[t * HID + c];
    const float bs = bias[c];

    float vin[6][3];
    #pragma unroll
    for (int rr = 0; rr < 6; rr++) {
        int hh = h0 + rr - 1;
        #pragma unroll
        for (int cc = 0; cc < 3; cc++) {
            int xx = ww + cc - 1;
            vin[rr][cc] = (hh >= 0 && hh < 64 && xx >= 0 && xx < 64)
                ? __half2float(y[((size_t)(b * 4096 + hh * 64 + xx)) * HID + c]) : 0.f;
        }
    }
    #pragma unroll
    for (int p = 0; p < 4; p++) {
        float acc = bs;
        #pragma unroll
        for (int ky = 0; ky < 3; ky++)
            #pragma unroll
            for (int kx = 0; kx < 3; kx++)
                acc += vin[p + ky][kx] * wreg[ky * 3 + kx];
        float g = 0.5f * acc * (1.f + erff(acc * 0.70710678118654752f));
        outh[((size_t)(b * 4096 + (h0 + p) * 64 + ww)) * HID + c] = __float2half(g);
    }
}

// ---------------- host orchestration ----------------------------------------
#define GEMM_SMEM (98304 + 1024)

extern "C" void kernel_launch(void* const* d_in, const int* in_sizes, int n_in,
                              void* d_out, int out_size)
{
    const float* query = (const float*)d_in[0];
    const float* refp  = (const float*)d_in[1];
    const float* feat  = (const float*)d_in[2];
    const int wb = n_in - 20;
    const float* qn_g  = (const float*)d_in[wb + 0];
    const float* qn_b  = (const float*)d_in[wb + 1];
    const float* fn_g  = (const float*)d_in[wb + 2];
    const float* fn_b  = (const float*)d_in[wb + 3];
    const float* off_w = (const float*)d_in[wb + 4];
    const float* off_b = (const float*)d_in[wb + 5];
    const float* aw_w  = (const float*)d_in[wb + 6];
    const float* aw_b  = (const float*)d_in[wb + 7];
    const float* vp_w  = (const float*)d_in[wb + 8];
    const float* vp_b  = (const float*)d_in[wb + 9];
    const float* op_w  = (const float*)d_in[wb + 10];
    const float* op_b  = (const float*)d_in[wb + 11];
    const float* ffn_g = (const float*)d_in[wb + 12];
    const float* ffn_b = (const float*)d_in[wb + 13];
    const float* fc1_w = (const float*)d_in[wb + 14];
    const float* fc1_b = (const float*)d_in[wb + 15];
    const float* dw_w  = (const float*)d_in[wb + 16];
    const float* dw_b  = (const float*)d_in[wb + 17];
    const float* fc2_w = (const float*)d_in[wb + 18];
    const float* fc2_b = (const float*)d_in[wb + 19];

    static cudaStream_t s1 = nullptr, s2 = nullptr;
    static cudaEvent_t e0, ewfa, ev, ew;
    if (!s1) {
        cudaStreamCreateWithFlags(&s1, cudaStreamNonBlocking);
        cudaStreamCreateWithFlags(&s2, cudaStreamNonBlocking);
        cudaEventCreateWithFlags(&e0,   cudaEventDisableTiming);
        cudaEventCreateWithFlags(&ewfa, cudaEventDisableTiming);
        cudaEventCreateWithFlags(&ev,   cudaEventDisableTiming);
        cudaEventCreateWithFlags(&ew,   cudaEventDisableTiming);
        cudaFuncSetAttribute(mma_gemm, cudaFuncAttributeMaxDynamicSharedMemorySize, GEMM_SMEM);
    }

    float *fa, *fab, *x;
    __half *qh, *fnh, *vb, *sph, *xlh, *yh, *ygh;
    __half *wv, *wo, *wfa, *w1, *w2;
    cudaGetSymbolAddress((void**)&qh,  g_qh);
    cudaGetSymbolAddress((void**)&fnh, g_fnh); cudaGetSymbolAddress((void**)&vb,  g_vb);
    cudaGetSymbolAddress((void**)&fa,  g_fa);  cudaGetSymbolAddress((void**)&fab, g_fab);
    cudaGetSymbolAddress((void**)&sph, g_sph); cudaGetSymbolAddress((void**)&x,   g_x);
    cudaGetSymbolAddress((void**)&xlh, g_xlh); cudaGetSymbolAddress((void**)&yh,  g_yh);
    cudaGetSymbolAddress((void**)&ygh, g_ygh);
    cudaGetSymbolAddress((void**)&wv,  g_wv);  cudaGetSymbolAddress((void**)&wo,  g_wo);
    cudaGetSymbolAddress((void**)&wfa, g_wfa); cudaGetSymbolAddress((void**)&w1,  g_w1);
    cudaGetSymbolAddress((void**)&w2,  g_w2);

    // fork
    cudaEventRecord(e0, 0);
    cudaStreamWaitEvent(s1, e0, 0);
    cudaStreamWaitEvent(s2, e0, 0);

    // s1: value branch (critical path)
    wprep_kernel<<<(768*768 + 255)/256, 256, 0, s1>>>(vp_w, wv, 768, 768, 768);
    ln_kernel<<<MV/16, 512, 0, s1>>>(feat, fn_g, fn_b, fnh);
    mma_gemm<<<dim3(6, MV/128), 256, GEMM_SMEM, s1>>>(fnh, wv, vp_b, nullptr, nullptr,
                                                      nullptr, vb, 1, MV, 768, 768, 768);
    cudaEventRecord(ev, s1);

    // s2: remaining weight preps
    wprep_merged_kernel<<<(256*768 + 255)/256, 256, 0, s2>>>(off_w, aw_w, wfa);
    biascat_kernel<<<1, 256, 0, s2>>>(off_b, aw_b, fab);
    cudaEventRecord(ewfa, s2);
    wprep_kernel<<<(768*768 + 255)/256, 256, 0, s2>>>(op_w,  wo, 768, 768, 768);
    wprep_kernel<<<(256*768 + 255)/256, 256, 0, s2>>>(fc1_w, w1, 192, 256, 768);
    wprep_kernel<<<(768*192 + 255)/256, 256, 0, s2>>>(fc2_w, w2, 768, 768, 192);
    cudaEventRecord(ew, s2);

    // s0: query branch + sampling + tail
    ln_kernel<<<MQ/16, 512>>>(query, qn_g, qn_b, qh);
    cudaStreamWaitEvent(0, ewfa, 0);
    mma_gemm<<<dim3(2, MQ/128), 256, GEMM_SMEM>>>(qh, wfa, fab, nullptr, nullptr,
                                                  fa, nullptr, 0, MQ, NFA, NFA, 768);
    cudaStreamWaitEvent(0, ev, 0);
    sample_kernel<<<MQ/2, 384>>>(refp, fa, vb, sph);
    cudaStreamWaitEvent(0, ew, 0);
    // x = query + LN(query) + samp@op_w + op_b   (residual q taken from fp16 qh)
    mma_gemm<<<dim3(6, MQ/128), 256, GEMM_SMEM>>>(sph, wo, op_b, qh, query,
                                                  x, nullptr, 0, MQ, 768, 768, 768);
    ln_kernel<<<MQ/16, 512>>>(x, ffn_g, ffn_b, xlh);
    mma_gemm<<<dim3(2, MQ/128), 256, GEMM_SMEM>>>(xlh, w1, fc1_b, nullptr, nullptr,
                                                  nullptr, yh, 0, MQ, 192, 192, 768);
    dwconv_gelu_kernel<<<BATCH*16*64, HID>>>(yh, dw_w, dw_b, ygh);
    mma_gemm<<<dim3(6, MQ/128), 256, GEMM_SMEM>>>(ygh, w2, fc2_b, nullptr, x,
                                                  (float*)d_out, nullptr, 0, MQ, 768, 768, 192);
}